// round 2
// baseline (speedup 1.0000x reference)
#include <cuda_runtime.h>
#include <cuda.h>
#include <cstdint>

// ============================================================================
// Scratch (device globals — no runtime allocation allowed)
// ============================================================================
__device__ __align__(1024) float g_T2[64 * 64 * 64];          // 1 MB
__device__ __align__(1024) float g_T3[64 * 64 * 64 * 64];     // 64 MB
__device__ __align__(1024) float g_W[4096 * 4096];            // 64 MB, row-major (O, I), tf32-rounded
__device__ __align__(1024) float g_Xr[16384 * 4096];          // 256 MB, x rounded to tf32

// ============================================================================
// PTX helpers (base compute_103 ISA only — NO tcgen05/'a' features)
// ============================================================================
__device__ __forceinline__ uint32_t elect_one_pred() {
    uint32_t pred;
    asm volatile(
        "{\n\t.reg .pred p;\n\t"
        "elect.sync _|p, 0xFFFFFFFF;\n\t"
        "selp.b32 %0, 1, 0, p;\n\t}"
        : "=r"(pred));
    return pred;
}

__device__ __forceinline__ uint32_t smem_to_u32(const void* smem_ptr) {
    uint32_t addr;
    asm("{ .reg .u64 tmp; cvta.to.shared.u64 tmp, %1; cvt.u32.u64 %0, tmp; }"
        : "=r"(addr) : "l"(smem_ptr));
    return addr;
}

#define MBARRIER_INIT(mbar, count) \
    asm volatile("mbarrier.init.shared.b64 [%0], %1;" \
        :: "r"((uint32_t)(mbar)), "r"((uint32_t)(count)) : "memory")

#define MBARRIER_ARRIVE(mbar) \
    asm volatile("mbarrier.arrive.shared.b64 _, [%0];" \
        :: "r"((uint32_t)(mbar)) : "memory")

#define MBARRIER_EXPECT_TX(mbar, tx_bytes) \
    asm volatile("mbarrier.arrive.expect_tx.shared.b64 _, [%0], %1;" \
        :: "r"((uint32_t)(mbar)), "r"((uint32_t)(tx_bytes)) : "memory")

#define MBARRIER_WAIT_PARITY(mbar, phase_parity) do { \
    uint32_t _mbar = (uint32_t)(mbar); \
    uint32_t _parity = (uint32_t)(phase_parity); \
    uint32_t _done; \
    asm volatile( \
        "{\n\t.reg .pred p;\n\t" \
        "mbarrier.try_wait.parity.acquire.cta.shared::cta.b64 p, [%1], %2;\n\t" \
        "selp.b32 %0, 1, 0, p;\n\t}" \
        : "=r"(_done) : "r"(_mbar), "r"(_parity) : "memory"); \
    if (!_done) { \
        asm volatile( \
            "{\n\t.reg .pred P1;\n\t" \
            "WAIT_LOOP_%=:\n\t" \
            "mbarrier.try_wait.parity.acquire.cta.shared::cta.b64 P1, [%0], %1, 0x989680;\n\t" \
            "@P1 bra.uni WAIT_DONE_%=;\n\t" \
            "bra.uni WAIT_LOOP_%=;\n\t" \
            "WAIT_DONE_%=:\n\t}" \
            :: "r"(_mbar), "r"(_parity) : "memory"); \
    } \
} while (0)

#define MBARRIER_WAIT_PARITY_RELAXED(mbar, phase_parity) do { \
    uint32_t _mbar = (uint32_t)(mbar); \
    uint32_t _parity = (uint32_t)(phase_parity); \
    uint32_t _done; \
    asm volatile( \
        "{\n\t.reg .pred p;\n\t" \
        "mbarrier.try_wait.parity.relaxed.cta.shared::cta.b64 p, [%1], %2, 0x989680;\n\t" \
        "selp.b32 %0, 1, 0, p;\n\t}" \
        : "=r"(_done) : "r"(_mbar), "r"(_parity) : "memory"); \
    if (!_done) { \
        asm volatile( \
            "{\n\t.reg .pred P1;\n\t" \
            "WAIT_LOOP_%=:\n\t" \
            "mbarrier.try_wait.parity.relaxed.cta.shared::cta.b64 P1, [%0], %1, 0x989680;\n\t" \
            "@P1 bra.uni WAIT_DONE_%=;\n\t" \
            "bra.uni WAIT_LOOP_%=;\n\t" \
            "WAIT_DONE_%=:\n\t}" \
            :: "r"(_mbar), "r"(_parity) : "memory"); \
    } \
} while (0)

#define TMA_LOAD_2D(smem_addr, map_ptr, cx, cy, mbar) \
    asm volatile( \
        "cp.async.bulk.tensor.2d.shared::cta.global.tile.mbarrier::complete_tx::bytes " \
        "[%0], [%1, {%2, %3}], [%4];" \
        :: "r"((uint32_t)(smem_addr)), "l"(map_ptr), \
           "r"((int32_t)(cx)), "r"((int32_t)(cy)), "r"((uint32_t)(mbar)) : "memory")

#define LDSM_X4(r0, r1, r2, r3, addr) \
    asm volatile("ldmatrix.sync.aligned.m8n8.x4.shared.b16 {%0,%1,%2,%3}, [%4];" \
        : "=r"(r0), "=r"(r1), "=r"(r2), "=r"(r3) : "r"(addr))

#define LDSM_X2(r0, r1, addr) \
    asm volatile("ldmatrix.sync.aligned.m8n8.x2.shared.b16 {%0,%1}, [%2];" \
        : "=r"(r0), "=r"(r1) : "r"(addr))

__device__ __forceinline__ void mma_tf32(float* c, const uint32_t* a, const uint32_t* b) {
    asm volatile(
        "mma.sync.aligned.m16n8k8.row.col.f32.tf32.tf32.f32 "
        "{%0,%1,%2,%3}, {%4,%5,%6,%7}, {%8,%9}, {%0,%1,%2,%3};"
        : "+f"(c[0]), "+f"(c[1]), "+f"(c[2]), "+f"(c[3])
        : "r"(a[0]), "r"(a[1]), "r"(a[2]), "r"(a[3]), "r"(b[0]), "r"(b[1]));
}

// ============================================================================
// W reconstruction from TT cores (fp32 chain, final rounded to tf32-nearest)
//   core0: (1,8,8,64)  [a=(i1*8+o1)][r1]
//   core1: (64,8,8,64) [r1][b=(i2*8+o2)][r2]
//   core2: (64,8,8,64) [r2][c=(i3*8+o3)][r3]
//   core3: (64,8,8,1)  [r3][d=(i4*8+o4)]
// ============================================================================
__global__ void build_T2(const float* __restrict__ c0, const float* __restrict__ c1) {
    int idx = blockIdx.x * 256 + threadIdx.x;          // 64*64*64
    int r2 = idx & 63, b = (idx >> 6) & 63, a = idx >> 12;
    float s = 0.f;
#pragma unroll 8
    for (int r1 = 0; r1 < 64; r1++)
        s += c0[a * 64 + r1] * c1[r1 * 4096 + b * 64 + r2];
    g_T2[idx] = s;
}

__global__ void build_T3(const float* __restrict__ c2) {
    int idx = blockIdx.x * 256 + threadIdx.x;          // 64^4
    int r3 = idx & 63, c = (idx >> 6) & 63, ab = idx >> 12;
    float s = 0.f;
#pragma unroll 8
    for (int r2 = 0; r2 < 64; r2++)
        s += g_T2[ab * 64 + r2] * c2[r2 * 4096 + c * 64 + r3];
    g_T3[idx] = s;
}

__global__ void build_W(const float* __restrict__ c3) {
    int idx = blockIdx.x * 256 + threadIdx.x;          // o*4096 + i
    int o = idx >> 12, i = idx & 4095;
    int o1 = (o >> 9) & 7, o2 = (o >> 6) & 7, o3 = (o >> 3) & 7, o4 = o & 7;
    int i1 = (i >> 9) & 7, i2 = (i >> 6) & 7, i3 = (i >> 3) & 7, i4 = i & 7;
    int a = i1 * 8 + o1, b = i2 * 8 + o2, c = i3 * 8 + o3, d = i4 * 8 + o4;
    const float* t3 = &g_T3[(((a * 64 + b) * 64 + c) * 64)];
    float s = 0.f;
#pragma unroll 8
    for (int r3 = 0; r3 < 64; r3++)
        s += t3[r3] * c3[r3 * 64 + d];
    uint32_t w32;
    asm("cvt.rna.tf32.f32 %0, %1;" : "=r"(w32) : "f"(s));   // RN to tf32
    g_W[idx] = __uint_as_float(w32);
}

// Pre-round x to tf32 (RN) — removes the truncation bias of the MMA's bit-drop
__global__ void round_x(const float* __restrict__ x, int n4) {
    int i = blockIdx.x * 256 + threadIdx.x;
    if (i < n4) {
        float4 v = ((const float4*)x)[i];
        uint4 o;
        asm("cvt.rna.tf32.f32 %0, %1;" : "=r"(o.x) : "f"(v.x));
        asm("cvt.rna.tf32.f32 %0, %1;" : "=r"(o.y) : "f"(v.y));
        asm("cvt.rna.tf32.f32 %0, %1;" : "=r"(o.z) : "f"(v.z));
        asm("cvt.rna.tf32.f32 %0, %1;" : "=r"(o.w) : "f"(v.w));
        ((uint4*)g_Xr)[i] = o;
    }
}

// ============================================================================
// Main GEMM: out[m, o] = sum_i x[m,i] * W[o,i] + bias[o]
// CTA 128(M) x 256(N) x 32(K), 16 compute warps (warp tile 64x32) + 1 TMA warp,
// 3-stage TMA/mbarrier pipeline, SW128 swizzle, ldmatrix + mma.sync tf32.
// ============================================================================
static constexpr int TILE_M = 128, TILE_N = 256, TILE_K = 32;
static constexpr int STAGES = 3;
static constexpr int NKCH = 4096 / TILE_K;            // 128
static constexpr int A_BYTES = TILE_M * TILE_K * 4;   // 16384
static constexpr int B_BYTES = TILE_N * TILE_K * 4;   // 32768
static constexpr int STAGE_BYTES = A_BYTES + B_BYTES; // 49152
static constexpr int OFF_FULL = 0;    // 3 x 8B
static constexpr int OFF_EMPTY = 64;  // 3 x 8B
static constexpr int OFF_DATA = 1024;
static constexpr int SMEM_BYTES = OFF_DATA + STAGES * STAGE_BYTES; // 148480
static constexpr int NTHREADS = 544;  // 16 compute warps + 1 producer warp

__global__ void __launch_bounds__(NTHREADS, 1) mpo_gemm(
    const __grid_constant__ CUtensorMap tmx,
    const __grid_constant__ CUtensorMap tmw,
    const float* __restrict__ bias,
    float* __restrict__ out)
{
    extern __shared__ __align__(1024) char smem[];
    const uint32_t sb = smem_to_u32(smem);
    const int tid  = threadIdx.x;
    const int wid  = tid >> 5, lane = tid & 31;
    const int nt_b = blockIdx.x;   // N tile (16) fastest -> x panel shared in L2
    const int mt_b = blockIdx.y;   // M tile (128)

    if (tid == 0) {
        for (int s = 0; s < STAGES; s++) {
            MBARRIER_INIT(sb + OFF_FULL + 8 * s, 1);    // TMA expect_tx path
            MBARRIER_INIT(sb + OFF_EMPTY + 8 * s, 16);  // one arrive per compute warp
        }
    }
    __syncthreads();

    if (wid == 16) {
        // ---------------- TMA producer warp ----------------
        if (elect_one_pred()) {
            int s = 0;
            for (int j = 0; j < NKCH; j++) {
                if (j >= STAGES)
                    MBARRIER_WAIT_PARITY_RELAXED(sb + OFF_EMPTY + 8 * s,
                                                 ((j / STAGES) - 1) & 1);
                MBARRIER_EXPECT_TX(sb + OFF_FULL + 8 * s, STAGE_BYTES);
                const uint32_t a_s = sb + OFF_DATA + s * STAGE_BYTES;
                TMA_LOAD_2D(a_s,           &tmx, j * TILE_K, mt_b * TILE_M,
                            sb + OFF_FULL + 8 * s);
                TMA_LOAD_2D(a_s + A_BYTES, &tmw, j * TILE_K, nt_b * TILE_N,
                            sb + OFF_FULL + 8 * s);
                if (++s == STAGES) s = 0;
            }
        }
        return;
    }

    // ---------------- compute warps (16): warp tile 64(M) x 32(N) ----------------
    const int wm = wid >> 3;        // 0..1
    const int wn = wid & 7;         // 0..7
    const int lr = lane & 7;        // row within ldmatrix tile
    const int t8 = lane >> 3;       // ldmatrix tile index 0..3
    const uint32_t axor = (uint32_t)lr << 4;            // SW128: 16B-chunk ^ (row&7)

    uint32_t arow[4], brow[4];
#pragma unroll
    for (int mt = 0; mt < 4; mt++)
        arow[mt] = (uint32_t)(wm * 64 + mt * 16 + (t8 & 1) * 8 + lr) * 128u;
#pragma unroll
    for (int nt = 0; nt < 4; nt++)
        brow[nt] = (uint32_t)(wn * 32 + nt * 8 + lr) * 128u;
    const uint32_t acol = (uint32_t)(t8 >> 1) << 4;
    const uint32_t bcol = (uint32_t)(t8 & 1) << 4;

    float acc[4][4][4];
#pragma unroll
    for (int mt = 0; mt < 4; mt++)
#pragma unroll
        for (int nt = 0; nt < 4; nt++)
#pragma unroll
            for (int e = 0; e < 4; e++) acc[mt][nt][e] = 0.f;

    int s = 0, ph = 0;
    for (int i = 0; i < NKCH; i++) {
        const uint32_t As = sb + OFF_DATA + s * STAGE_BYTES;
        const uint32_t Bs = As + A_BYTES;
        MBARRIER_WAIT_PARITY(sb + OFF_FULL + 8 * s, ph);
#pragma unroll
        for (int ks = 0; ks < 4; ks++) {
            const uint32_t acolk = ((uint32_t)(ks * 32) + acol) ^ axor;
            const uint32_t bcolk = ((uint32_t)(ks * 32) + bcol) ^ axor;
            uint32_t a[4][4], b[4][2];
#pragma unroll
            for (int mt = 0; mt < 4; mt++)
                LDSM_X4(a[mt][0], a[mt][1], a[mt][2], a[mt][3],
                        As + arow[mt] + acolk);
#pragma unroll
            for (int nt = 0; nt < 4; nt++)
                LDSM_X2(b[nt][0], b[nt][1], Bs + brow[nt] + bcolk);
#pragma unroll
            for (int mt = 0; mt < 4; mt++)
#pragma unroll
                for (int nt = 0; nt < 4; nt++)
                    mma_tf32(acc[mt][nt], a[mt], b[nt]);
        }
        if (elect_one_pred()) MBARRIER_ARRIVE(sb + OFF_EMPTY + 8 * s);
        if (++s == STAGES) { s = 0; ph ^= 1; }
    }

    // ---------------- epilogue: + bias, write fp32 ----------------
    const int m0 = mt_b * TILE_M + wm * 64;
    const int n0 = nt_b * TILE_N + wn * 32;
    const int rr = lane >> 2;
    const int cc = (lane & 3) * 2;
#pragma unroll
    for (int nt = 0; nt < 4; nt++) {
        const int col = n0 + nt * 8 + cc;
        const float2 bv = *(const float2*)&bias[col];
#pragma unroll
        for (int mt = 0; mt < 4; mt++) {
            const int r0 = m0 + mt * 16 + rr;
            float2 v0, v1;
            v0.x = acc[mt][nt][0] + bv.x;  v0.y = acc[mt][nt][1] + bv.y;
            v1.x = acc[mt][nt][2] + bv.x;  v1.y = acc[mt][nt][3] + bv.y;
            *(float2*)&out[(size_t)r0 * 4096 + col]       = v0;
            *(float2*)&out[(size_t)(r0 + 8) * 4096 + col] = v1;
        }
    }
}

// ============================================================================
// Host launcher
// ============================================================================
typedef CUresult (*TmapEncodeFn)(
    CUtensorMap*, CUtensorMapDataType, cuuint32_t, void*,
    const cuuint64_t*, const cuuint64_t*, const cuuint32_t*, const cuuint32_t*,
    CUtensorMapInterleave, CUtensorMapSwizzle, CUtensorMapL2promotion,
    CUtensorMapFloatOOBfill);

extern "C" void kernel_launch(void* const* d_in, const int* in_sizes, int n_in,
                              void* d_out, int out_size) {
    const float* x    = (const float*)d_in[0];
    const float* c0   = (const float*)d_in[1];
    const float* c1   = (const float*)d_in[2];
    const float* c2   = (const float*)d_in[3];
    const float* c3   = (const float*)d_in[4];
    const float* bias = (const float*)d_in[5];
    float* out = (float*)d_out;

    const int M = in_sizes[0] / 4096;   // 16384 rows of x

    // --- W reconstruction (~4.3 GFLOP) + x rounding ---
    build_T2<<<(64 * 64 * 64) / 256, 256>>>(c0, c1);
    build_T3<<<(1 << 24) / 256, 256>>>(c2);
    build_W<<<(1 << 24) / 256, 256>>>(c3);
    round_x<<<(M * 4096 / 4 + 255) / 256, 256>>>(x, M * 4096 / 4);

    // --- TMA descriptors (driver API via runtime entry point; no -lcuda) ---
    TmapEncodeFn enc = nullptr;
    cudaDriverEntryPointQueryResult st;
#if CUDART_VERSION >= 12050
    cudaGetDriverEntryPointByVersion("cuTensorMapEncodeTiled", (void**)&enc,
                                     12000, cudaEnableDefault, &st);
#else
    cudaGetDriverEntryPoint("cuTensorMapEncodeTiled", (void**)&enc,
                            cudaEnableDefault, &st);
#endif

    void* wptr = nullptr;
    void* xptr = nullptr;
    cudaGetSymbolAddress(&wptr, g_W);
    cudaGetSymbolAddress(&xptr, g_Xr);

    CUtensorMap tmx{}, tmw{};
    {
        cuuint64_t dims[2]    = {4096ull, (cuuint64_t)M};
        cuuint64_t strides[1] = {4096ull * 4ull};
        cuuint32_t box[2]     = {TILE_K, TILE_M};   // 32 floats (=128B) x 128 rows
        cuuint32_t es[2]      = {1, 1};
        enc(&tmx, CU_TENSOR_MAP_DATA_TYPE_FLOAT32, 2, xptr,
            dims, strides, box, es,
            CU_TENSOR_MAP_INTERLEAVE_NONE, CU_TENSOR_MAP_SWIZZLE_128B,
            CU_TENSOR_MAP_L2_PROMOTION_L2_128B, CU_TENSOR_MAP_FLOAT_OOB_FILL_NONE);
    }
    {
        cuuint64_t dims[2]    = {4096ull, 4096ull};
        cuuint64_t strides[1] = {4096ull * 4ull};
        cuuint32_t box[2]     = {TILE_K, TILE_N};   // 32 floats x 256 rows
        cuuint32_t es[2]      = {1, 1};
        enc(&tmw, CU_TENSOR_MAP_DATA_TYPE_FLOAT32, 2, wptr,
            dims, strides, box, es,
            CU_TENSOR_MAP_INTERLEAVE_NONE, CU_TENSOR_MAP_SWIZZLE_128B,
            CU_TENSOR_MAP_L2_PROMOTION_L2_128B, CU_TENSOR_MAP_FLOAT_OOB_FILL_NONE);
    }

    cudaFuncSetAttribute(mpo_gemm, cudaFuncAttributeMaxDynamicSharedMemorySize,
                         SMEM_BYTES);
    dim3 grid(4096 / TILE_N, M / TILE_M);   // (16, 128)
    mpo_gemm<<<grid, NTHREADS, SMEM_BYTES>>>(tmx, tmw, bias, out);
}